// round 2
// baseline (speedup 1.0000x reference)
#include <cuda_runtime.h>
#include <cuda_bf16.h>

// ---------------- scratch (device globals; no allocs allowed) ----------------
__device__ __align__(16) float g_T1[4 * 132 * 64];     // conv1 tap table: [tap][combo][oc]
__device__ __align__(16) float g_GI[100 * 384];        // GRU input proj table: [word][gate]
__device__ __align__(16) float g_ht[8192 * 128];       // GRU final hidden per batch

// ---------------- helpers ----------------
__device__ __forceinline__ float sigm_(float x) { return 1.0f / (1.0f + __expf(-x)); }
__device__ __forceinline__ float tanh_(float x) { return 2.0f / (1.0f + __expf(-2.0f * x)) - 1.0f; }

// ---------------- K1: conv1 tap table ----------------
// T1[tap][combo][oc] = sum_k conv1_w[oc][k][ty][tx] * embvec[combo][k]
// embvec = concat(col_emb[col], obj_emb[obj], st_emb[st]); combo = (obj*6+col)*2+st
__global__ void k_build_t1(const float* __restrict__ obj_emb,
                           const float* __restrict__ col_emb,
                           const float* __restrict__ st_emb,
                           const float* __restrict__ w1) {
    int blk = blockIdx.x;            // 0..527 = tap*132 + combo
    int tap = blk / 132, combo = blk % 132;
    int ty = tap >> 1, tx = tap & 1;
    int s = combo & 1;
    int q = combo >> 1;
    int cc = q % 6, o = q / 6;
    __shared__ __align__(16) float ev[48];
    int t = threadIdx.x;             // 64 threads
    if (t < 16)       ev[t] = col_emb[cc * 16 + t];
    else if (t < 32)  ev[t] = obj_emb[o * 16 + (t - 16)];
    else if (t < 48)  ev[t] = st_emb[s * 16 + (t - 32)];
    __syncthreads();
    float v = 0.f;
    #pragma unroll 8
    for (int k = 0; k < 48; k++)
        v += w1[((t * 48 + k) * 2 + ty) * 2 + tx] * ev[k];
    g_T1[(tap * 132 + combo) * 64 + t] = v;
}

// ---------------- K2: GRU input-projection table ----------------
// GI[v][g] = gru_bih[g] + sum_k gru_wih[g][k] * word_emb[v][k]
__global__ void k_build_gi(const float* __restrict__ word_emb,
                           const float* __restrict__ gwih,
                           const float* __restrict__ gbih) {
    int v = blockIdx.x;              // 100
    int g = threadIdx.x;             // 384
    __shared__ __align__(16) float ev[32];
    if (g < 32) ev[g] = word_emb[v * 32 + g];
    __syncthreads();
    float a = gbih[g];
    const float* w = gwih + g * 32;
    #pragma unroll 8
    for (int k = 0; k < 32; k++) a += w[k] * ev[k];
    g_GI[v * 384 + g] = a;
}

// ---------------- K3: conv stack + LSTM (1 batch elem / block, 128 threads) ----
__global__ __launch_bounds__(128)
void k_conv_lstm(const int* __restrict__ image, const float* __restrict__ memory,
                 const float* __restrict__ b1,
                 const float* __restrict__ w2, const float* __restrict__ b2,
                 const float* __restrict__ w3, const float* __restrict__ b3,
                 const float* __restrict__ wih, const float* __restrict__ whh,
                 const float* __restrict__ bih, const float* __restrict__ bhh,
                 float* __restrict__ mem_out) {
    int b = blockIdx.x, t = threadIdx.x;
    __shared__ __align__(16) int   s_combo[49];
    __shared__ __align__(16) float s_c1[64 * 36];   // [c][y*6+x]
    __shared__ __align__(16) float s_p[64 * 9];     // [c][y*3+x]
    __shared__ __align__(16) float s_q[64 * 4];     // [c][y*2+x]
    __shared__ __align__(16) float s_x[128];
    __shared__ __align__(16) float s_h[128];

    if (t < 49) {
        const int* px = image + (b * 49 + t) * 3;
        s_combo[t] = (px[0] * 6 + px[1]) * 2 + px[2];
    }
    s_h[t] = memory[b * 256 + t];
    __syncthreads();

    // conv1 via tap table + relu  (2304 outputs)
    for (int idx = t; idx < 64 * 36; idx += 128) {
        int c = idx / 36, pos = idx % 36;
        int y = pos / 6, x = pos % 6;
        float v = b1[c];
        v += g_T1[(0 * 132 + s_combo[y * 7 + x]) * 64 + c];
        v += g_T1[(1 * 132 + s_combo[y * 7 + x + 1]) * 64 + c];
        v += g_T1[(2 * 132 + s_combo[(y + 1) * 7 + x]) * 64 + c];
        v += g_T1[(3 * 132 + s_combo[(y + 1) * 7 + x + 1]) * 64 + c];
        s_c1[c * 36 + pos] = fmaxf(v, 0.f);
    }
    __syncthreads();

    // maxpool 2x2 stride 2 -> (64,3,3)
    for (int idx = t; idx < 64 * 9; idx += 128) {
        int c = idx / 9, pos = idx % 9;
        int y = pos / 3, x = pos % 3;
        const float* base = s_c1 + c * 36 + (2 * y) * 6 + 2 * x;
        s_p[idx] = fmaxf(fmaxf(base[0], base[1]), fmaxf(base[6], base[7]));
    }
    __syncthreads();

    // conv2 2x2 -> (64,2,2) + relu
    for (int idx = t; idx < 256; idx += 128) {
        int c = idx / 4, pos = idx % 4;
        int y = pos / 2, x = pos % 2;
        float v = b2[c];
        const float* wrow = w2 + c * 256;
        #pragma unroll 8
        for (int ci = 0; ci < 64; ci++) {
            const float* pp = s_p + ci * 9 + y * 3 + x;
            float4 w4 = *(const float4*)(wrow + ci * 4);
            v += w4.x * pp[0] + w4.y * pp[1] + w4.z * pp[3] + w4.w * pp[4];
        }
        s_q[c * 4 + pos] = fmaxf(v, 0.f);
    }
    __syncthreads();

    // conv3 2x2 -> (128,) + relu
    {
        float v = b3[t];
        const float* wrow = w3 + t * 256;
        #pragma unroll 8
        for (int ci = 0; ci < 64; ci++) {
            float4 w4 = *(const float4*)(wrow + ci * 4);
            float4 q4 = *(const float4*)(s_q + ci * 4);
            v += w4.x * q4.x + w4.y * q4.y + w4.z * q4.z + w4.w * q4.w;
        }
        s_x[t] = fmaxf(v, 0.f);
    }
    __syncthreads();

    // LSTM cell: thread t owns hidden unit t (gates i,f,g,o = rows t, 128+t, 256+t, 384+t)
    {
        int j = t;
        float gi = bih[j]       + bhh[j];
        float gf = bih[128 + j] + bhh[128 + j];
        float gg = bih[256 + j] + bhh[256 + j];
        float go = bih[384 + j] + bhh[384 + j];
        const float* wi0 = wih + j * 128;
        const float* wi1 = wih + (128 + j) * 128;
        const float* wi2 = wih + (256 + j) * 128;
        const float* wi3 = wih + (384 + j) * 128;
        const float* wh0 = whh + j * 128;
        const float* wh1 = whh + (128 + j) * 128;
        const float* wh2 = whh + (256 + j) * 128;
        const float* wh3 = whh + (384 + j) * 128;
        for (int k = 0; k < 128; k += 4) {
            float4 xv = *(const float4*)(s_x + k);
            float4 hv = *(const float4*)(s_h + k);
            float4 a;
            a = *(const float4*)(wi0 + k); gi += a.x*xv.x + a.y*xv.y + a.z*xv.z + a.w*xv.w;
            a = *(const float4*)(wh0 + k); gi += a.x*hv.x + a.y*hv.y + a.z*hv.z + a.w*hv.w;
            a = *(const float4*)(wi1 + k); gf += a.x*xv.x + a.y*xv.y + a.z*xv.z + a.w*xv.w;
            a = *(const float4*)(wh1 + k); gf += a.x*hv.x + a.y*hv.y + a.z*hv.z + a.w*hv.w;
            a = *(const float4*)(wi2 + k); gg += a.x*xv.x + a.y*xv.y + a.z*xv.z + a.w*xv.w;
            a = *(const float4*)(wh2 + k); gg += a.x*hv.x + a.y*hv.y + a.z*hv.z + a.w*hv.w;
            a = *(const float4*)(wi3 + k); go += a.x*xv.x + a.y*xv.y + a.z*xv.z + a.w*xv.w;
            a = *(const float4*)(wh3 + k); go += a.x*hv.x + a.y*hv.y + a.z*hv.z + a.w*hv.w;
        }
        float c_in = memory[b * 256 + 128 + j];
        float cn = sigm_(gf) * c_in + sigm_(gi) * tanh_(gg);
        float hn = sigm_(go) * tanh_(cn);
        mem_out[b * 256 + j] = hn;
        mem_out[b * 256 + 128 + j] = cn;
    }
}

// ---------------- K4: GRU over 20 steps (8 batch / block, 128 threads) --------
__global__ __launch_bounds__(128)
void k_gru(const int* __restrict__ text, const float* __restrict__ whh,
           const float* __restrict__ bhh) {
    int j = threadIdx.x;                 // hidden unit
    int b0 = blockIdx.x * 8;
    __shared__ __align__(16) float s_ht[8 * 128];
    __shared__ __align__(16) int s_w[8 * 20];
    for (int idx = j; idx < 160; idx += 128) s_w[idx] = text[b0 * 20 + idx];
    #pragma unroll
    for (int bi = 0; bi < 8; bi++) s_ht[bi * 128 + j] = 0.f;
    float htj[8];
    #pragma unroll
    for (int bi = 0; bi < 8; bi++) htj[bi] = 0.f;

    float bh_r = bhh[j], bh_z = bhh[128 + j], bh_n = bhh[256 + j];
    const float* wr = whh + j * 128;
    const float* wz = whh + (128 + j) * 128;
    const float* wn = whh + (256 + j) * 128;
    __syncthreads();

    for (int tt = 0; tt < 20; tt++) {
        float ar[8], az[8], an[8];
        #pragma unroll
        for (int bi = 0; bi < 8; bi++) { ar[bi] = bh_r; az[bi] = bh_z; an[bi] = bh_n; }
        for (int k = 0; k < 128; k += 4) {
            float4 w4r = *(const float4*)(wr + k);
            float4 w4z = *(const float4*)(wz + k);
            float4 w4n = *(const float4*)(wn + k);
            #pragma unroll
            for (int bi = 0; bi < 8; bi++) {
                float4 hv = *(const float4*)(s_ht + bi * 128 + k);
                ar[bi] += w4r.x*hv.x + w4r.y*hv.y + w4r.z*hv.z + w4r.w*hv.w;
                az[bi] += w4z.x*hv.x + w4z.y*hv.y + w4z.z*hv.z + w4z.w*hv.w;
                an[bi] += w4n.x*hv.x + w4n.y*hv.y + w4n.z*hv.z + w4n.w*hv.w;
            }
        }
        __syncthreads();   // all reads of s_ht complete
        #pragma unroll
        for (int bi = 0; bi < 8; bi++) {
            const float* gi = g_GI + s_w[bi * 20 + tt] * 384;
            float r = sigm_(gi[j] + ar[bi]);
            float z = sigm_(gi[128 + j] + az[bi]);
            float n = tanh_(gi[256 + j] + r * an[bi]);
            float h = (1.f - z) * n + z * htj[bi];
            htj[bi] = h;
            s_ht[bi * 128 + j] = h;
        }
        __syncthreads();   // writes visible
    }
    #pragma unroll
    for (int bi = 0; bi < 8; bi++) g_ht[(b0 + bi) * 128 + j] = htj[bi];
}

// ---------------- K5: actor/critic heads (16 batch / block, 256 threads) -----
__global__ __launch_bounds__(256)
void k_heads(const float* __restrict__ mem,
             const float* __restrict__ aw1, const float* __restrict__ ab1,
             const float* __restrict__ aw2, const float* __restrict__ ab2,
             const float* __restrict__ cw1, const float* __restrict__ cb1,
             const float* __restrict__ cw2, const float* __restrict__ cb2,
             float* __restrict__ lp, float* __restrict__ value) {
    int tid = threadIdx.x;           // 256
    int b0 = blockIdx.x * 16;
    __shared__ __align__(16) float s_emb[16 * 256];
    __shared__ __align__(16) float s_a1[16 * 256];
    __shared__ __align__(16) float s_logits[16 * 8];

    for (int idx = tid; idx < 16 * 128; idx += 256) {
        int bi = idx >> 7, k = idx & 127;
        s_emb[bi * 256 + k]       = mem[(b0 + bi) * 256 + k];   // LSTM h
        s_emb[bi * 256 + 128 + k] = g_ht[(b0 + bi) * 128 + k];  // GRU ht
    }
    __syncthreads();

    // actor layer 1: unit = tid
    {
        float acc[16];
        float bb = ab1[tid];
        #pragma unroll
        for (int bi = 0; bi < 16; bi++) acc[bi] = bb;
        const float* w = aw1 + tid * 256;
        for (int k = 0; k < 256; k += 4) {
            float4 w4 = *(const float4*)(w + k);
            #pragma unroll
            for (int bi = 0; bi < 16; bi++) {
                float4 e = *(const float4*)(s_emb + bi * 256 + k);
                acc[bi] += w4.x*e.x + w4.y*e.y + w4.z*e.z + w4.w*e.w;
            }
        }
        #pragma unroll
        for (int bi = 0; bi < 16; bi++) s_a1[bi * 256 + tid] = tanh_(acc[bi]);
    }
    __syncthreads();

    int warp = tid >> 5, lane = tid & 31;
    // logits: 8 warps, 2 batches each, 7 logits
    for (int bi = warp * 2; bi < warp * 2 + 2; bi++) {
        for (int a = 0; a < 7; a++) {
            float s = 0.f;
            for (int k = lane; k < 256; k += 32) s += aw2[a * 256 + k] * s_a1[bi * 256 + k];
            #pragma unroll
            for (int off = 16; off; off >>= 1) s += __shfl_xor_sync(0xffffffffu, s, off);
            if (lane == 0) s_logits[bi * 8 + a] = s + ab2[a];
        }
    }
    __syncthreads();

    // critic layer 1 (overwrites s_a1; logits already consumed into s_logits)
    {
        float acc[16];
        float bb = cb1[tid];
        #pragma unroll
        for (int bi = 0; bi < 16; bi++) acc[bi] = bb;
        const float* w = cw1 + tid * 256;
        for (int k = 0; k < 256; k += 4) {
            float4 w4 = *(const float4*)(w + k);
            #pragma unroll
            for (int bi = 0; bi < 16; bi++) {
                float4 e = *(const float4*)(s_emb + bi * 256 + k);
                acc[bi] += w4.x*e.x + w4.y*e.y + w4.z*e.z + w4.w*e.w;
            }
        }
        #pragma unroll
        for (int bi = 0; bi < 16; bi++) s_a1[bi * 256 + tid] = tanh_(acc[bi]);
    }
    // log_softmax (independent of s_a1 rewrite; reads s_logits)
    if (tid < 16) {
        float m = -1e30f;
        #pragma unroll
        for (int a = 0; a < 7; a++) m = fmaxf(m, s_logits[tid * 8 + a]);
        float sum = 0.f;
        #pragma unroll
        for (int a = 0; a < 7; a++) sum += expf(s_logits[tid * 8 + a] - m);
        float lse = m + logf(sum);
        #pragma unroll
        for (int a = 0; a < 7; a++) lp[(b0 + tid) * 7 + a] = s_logits[tid * 8 + a] - lse;
    }
    __syncthreads();

    // value: warp reduce over critic layer-1 output
    for (int bi = warp * 2; bi < warp * 2 + 2; bi++) {
        float s = 0.f;
        for (int k = lane; k < 256; k += 32) s += cw2[k] * s_a1[bi * 256 + k];
        #pragma unroll
        for (int off = 16; off; off >>= 1) s += __shfl_xor_sync(0xffffffffu, s, off);
        if (lane == 0) value[b0 + bi] = s + cb2[0];
    }
}

// ---------------- launch ----------------
extern "C" void kernel_launch(void* const* d_in, const int* in_sizes, int n_in,
                              void* d_out, int out_size) {
    const int*   image  = (const int*)  d_in[0];
    const float* memory = (const float*)d_in[1];
    const int*   text   = (const int*)  d_in[2];
    const float* obj_e  = (const float*)d_in[3];
    const float* col_e  = (const float*)d_in[4];
    const float* st_e   = (const float*)d_in[5];
    const float* c1w    = (const float*)d_in[6];
    const float* c1b    = (const float*)d_in[7];
    const float* c2w    = (const float*)d_in[8];
    const float* c2b    = (const float*)d_in[9];
    const float* c3w    = (const float*)d_in[10];
    const float* c3b    = (const float*)d_in[11];
    const float* lwih   = (const float*)d_in[12];
    const float* lwhh   = (const float*)d_in[13];
    const float* lbih   = (const float*)d_in[14];
    const float* lbhh   = (const float*)d_in[15];
    const float* wemb   = (const float*)d_in[16];
    const float* gwih   = (const float*)d_in[17];
    const float* gwhh   = (const float*)d_in[18];
    const float* gbih   = (const float*)d_in[19];
    const float* gbhh   = (const float*)d_in[20];
    const float* aw1    = (const float*)d_in[21];
    const float* ab1    = (const float*)d_in[22];
    const float* aw2    = (const float*)d_in[23];
    const float* ab2    = (const float*)d_in[24];
    const float* cw1    = (const float*)d_in[25];
    const float* cb1    = (const float*)d_in[26];
    const float* cw2    = (const float*)d_in[27];
    const float* cb2    = (const float*)d_in[28];

    const int B = in_sizes[1] / 256;   // 8192
    float* out   = (float*)d_out;
    float* lp    = out;                // (B,7)
    float* value = out + (size_t)B * 7;
    float* memo  = out + (size_t)B * 8; // (B,256)

    k_build_t1<<<4 * 132, 64>>>(obj_e, col_e, st_e, c1w);
    k_build_gi<<<100, 384>>>(wemb, gwih, gbih);
    k_conv_lstm<<<B, 128>>>(image, memory, c1b, c2w, c2b, c3w, c3b,
                            lwih, lwhh, lbih, lbhh, memo);
    k_gru<<<B / 8, 128>>>(text, gwhh, gbhh);
    k_heads<<<B / 16, 256>>>(memo, aw1, ab1, aw2, ab2, cw1, cb1, cw2, cb2,
                             lp, value);
}

// round 3
// speedup vs baseline: 4.0487x; 4.0487x over previous
#include <cuda_runtime.h>
#include <cuda_bf16.h>

// ---------------- scratch (device globals; no allocs allowed) ----------------
__device__ __align__(16) float g_T1[4 * 132 * 64];   // conv1 tap table [tap][combo][oc]
__device__ __align__(16) float g_GI[100 * 384];      // GRU input proj table [word][gate]
__device__ __align__(16) float g_ht[8192 * 128];     // GRU final hidden
__device__ __align__(16) float g_x[8192 * 128];      // conv output (LSTM input)
// transposed weights: dst[(k>>2)*N*4 + row*4 + (k&3)]
__device__ __align__(16) float g_wihT[512 * 128];
__device__ __align__(16) float g_whhT[512 * 128];
__device__ __align__(16) float g_gwhhT[384 * 128];
__device__ __align__(16) float g_aw1T[256 * 256];
__device__ __align__(16) float g_cw1T[256 * 256];
__device__ __align__(16) float g_w2T[64 * 256];
__device__ __align__(16) float g_w3T[128 * 256];

__device__ __forceinline__ float sigm_(float x) { return 1.0f / (1.0f + __expf(-x)); }
__device__ __forceinline__ float tanh_(float x) { return 2.0f / (1.0f + __expf(-2.0f * x)) - 1.0f; }

// ---------------- K0: generic transpose into chunk-of-4 interleaved layout ----
__global__ void k_xpose(const float* __restrict__ src, float* __restrict__ dst,
                        int N, int K) {
    int total = N * K;
    for (int idx = blockIdx.x * blockDim.x + threadIdx.x; idx < total;
         idx += gridDim.x * blockDim.x) {
        int j = idx / K, k = idx % K;
        dst[(k >> 2) * (N * 4) + j * 4 + (k & 3)] = src[idx];
    }
}

// ---------------- K1: conv1 tap table ----------------
__global__ void k_build_t1(const float* __restrict__ obj_emb,
                           const float* __restrict__ col_emb,
                           const float* __restrict__ st_emb,
                           const float* __restrict__ w1) {
    int blk = blockIdx.x;            // tap*132 + combo
    int tap = blk / 132, combo = blk % 132;
    int ty = tap >> 1, tx = tap & 1;
    int s = combo & 1;
    int q = combo >> 1;
    int cc = q % 6, o = q / 6;
    __shared__ __align__(16) float ev[48];
    int t = threadIdx.x;             // 64
    if (t < 16)       ev[t] = col_emb[cc * 16 + t];
    else if (t < 32)  ev[t] = obj_emb[o * 16 + (t - 16)];
    else if (t < 48)  ev[t] = st_emb[s * 16 + (t - 32)];
    __syncthreads();
    float v = 0.f;
    #pragma unroll 8
    for (int k = 0; k < 48; k++)
        v += w1[((t * 48 + k) * 2 + ty) * 2 + tx] * ev[k];
    g_T1[(tap * 132 + combo) * 64 + t] = v;
}

// ---------------- K2: GRU input-projection table ----------------
__global__ void k_build_gi(const float* __restrict__ word_emb,
                           const float* __restrict__ gwih,
                           const float* __restrict__ gbih) {
    int v = blockIdx.x;              // 100
    int g = threadIdx.x;             // 384
    __shared__ __align__(16) float ev[32];
    if (g < 32) ev[g] = word_emb[v * 32 + g];
    __syncthreads();
    float a = gbih[g];
    const float* w = gwih + g * 32;
    #pragma unroll 8
    for (int k = 0; k < 32; k++) a += w[k] * ev[k];
    g_GI[v * 384 + g] = a;
}

// ---------------- K3: conv stack (1 elem / block, 128 threads) ----------------
__global__ __launch_bounds__(128)
void k_conv(const int* __restrict__ image,
            const float* __restrict__ b1, const float* __restrict__ b2,
            const float* __restrict__ b3) {
    int b = blockIdx.x, t = threadIdx.x;
    __shared__ __align__(16) int   s_combo[49];
    __shared__ __align__(16) float s_c1[36 * 64];   // [pos][c]
    __shared__ __align__(16) float s_p[9 * 64];     // [pos][c]
    __shared__ __align__(16) float s_q[4 * 64];     // [pos][c]

    if (t < 49) {
        const int* px = image + (b * 49 + t) * 3;
        s_combo[t] = (px[0] * 6 + px[1]) * 2 + px[2];
    }
    __syncthreads();

    // conv1 via tap table + relu; lanes over channel c (coalesced T1 reads)
    for (int idx = t; idx < 36 * 64; idx += 128) {
        int c = idx & 63, pos = idx >> 6;
        int y = pos / 6, x = pos % 6;
        float v = b1[c];
        v += g_T1[(0 * 132 + s_combo[y * 7 + x]) * 64 + c];
        v += g_T1[(1 * 132 + s_combo[y * 7 + x + 1]) * 64 + c];
        v += g_T1[(2 * 132 + s_combo[(y + 1) * 7 + x]) * 64 + c];
        v += g_T1[(3 * 132 + s_combo[(y + 1) * 7 + x + 1]) * 64 + c];
        s_c1[pos * 64 + c] = fmaxf(v, 0.f);
    }
    __syncthreads();

    // maxpool 2x2 stride 2 -> (3,3,64)
    for (int idx = t; idx < 9 * 64; idx += 128) {
        int c = idx & 63, pos = idx >> 6;
        int y = pos / 3, x = pos % 3;
        int p0 = (2 * y) * 6 + 2 * x;
        float v = fmaxf(fmaxf(s_c1[p0 * 64 + c], s_c1[(p0 + 1) * 64 + c]),
                        fmaxf(s_c1[(p0 + 6) * 64 + c], s_c1[(p0 + 7) * 64 + c]));
        s_p[pos * 64 + c] = v;
    }
    __syncthreads();

    // conv2 2x2 -> (2,2,64) + relu; transposed weights coalesced over c
    for (int idx = t; idx < 256; idx += 128) {
        int c = idx & 63, pos = idx >> 6;
        int y = pos >> 1, x = pos & 1;
        float v = b2[c];
        int p00 = y * 3 + x;
        #pragma unroll 8
        for (int ci = 0; ci < 64; ci++) {
            float4 w4 = *(const float4*)(g_w2T + ci * 256 + c * 4);
            v += w4.x * s_p[p00 * 64 + ci] + w4.y * s_p[(p00 + 1) * 64 + ci]
               + w4.z * s_p[(p00 + 3) * 64 + ci] + w4.w * s_p[(p00 + 4) * 64 + ci];
        }
        s_q[pos * 64 + c] = fmaxf(v, 0.f);
    }
    __syncthreads();

    // conv3 2x2 -> (128,) + relu; thread t = output channel
    {
        float v = b3[t];
        #pragma unroll 8
        for (int ci = 0; ci < 64; ci++) {
            float4 w4 = *(const float4*)(g_w3T + ci * 512 + t * 4);
            v += w4.x * s_q[0 * 64 + ci] + w4.y * s_q[1 * 64 + ci]
               + w4.z * s_q[2 * 64 + ci] + w4.w * s_q[3 * 64 + ci];
        }
        g_x[b * 128 + t] = fmaxf(v, 0.f);
    }
}

// ---------------- K4: LSTM (8 elems/block, 128 threads) -----------------------
__global__ __launch_bounds__(128)
void k_lstm(const float* __restrict__ memory,
            const float* __restrict__ bih, const float* __restrict__ bhh,
            float* __restrict__ mem_out) {
    int j = threadIdx.x;
    int b0 = blockIdx.x * 8;
    __shared__ __align__(16) float s_x[8 * 128];
    __shared__ __align__(16) float s_h[8 * 128];
    for (int idx = j; idx < 8 * 128; idx += 128) {
        int bi = idx >> 7, k = idx & 127;
        s_x[idx] = g_x[(b0 + bi) * 128 + k];
        s_h[idx] = memory[(b0 + bi) * 256 + k];
    }
    float acc0[8], acc1[8], acc2[8], acc3[8];
    float bb0 = bih[j]       + bhh[j];
    float bb1 = bih[128 + j] + bhh[128 + j];
    float bb2 = bih[256 + j] + bhh[256 + j];
    float bb3 = bih[384 + j] + bhh[384 + j];
    #pragma unroll
    for (int bi = 0; bi < 8; bi++) { acc0[bi] = bb0; acc1[bi] = bb1; acc2[bi] = bb2; acc3[bi] = bb3; }
    __syncthreads();

    for (int k = 0; k < 128; k += 4) {
        int kc = k >> 2;
        float4 wi0 = *(const float4*)(g_wihT + kc * 2048 + j * 4);
        float4 wi1 = *(const float4*)(g_wihT + kc * 2048 + (128 + j) * 4);
        float4 wi2 = *(const float4*)(g_wihT + kc * 2048 + (256 + j) * 4);
        float4 wi3 = *(const float4*)(g_wihT + kc * 2048 + (384 + j) * 4);
        float4 wh0 = *(const float4*)(g_whhT + kc * 2048 + j * 4);
        float4 wh1 = *(const float4*)(g_whhT + kc * 2048 + (128 + j) * 4);
        float4 wh2 = *(const float4*)(g_whhT + kc * 2048 + (256 + j) * 4);
        float4 wh3 = *(const float4*)(g_whhT + kc * 2048 + (384 + j) * 4);
        #pragma unroll
        for (int bi = 0; bi < 8; bi++) {
            float4 xv = *(const float4*)(s_x + bi * 128 + k);
            float4 hv = *(const float4*)(s_h + bi * 128 + k);
            acc0[bi] += wi0.x*xv.x + wi0.y*xv.y + wi0.z*xv.z + wi0.w*xv.w
                      + wh0.x*hv.x + wh0.y*hv.y + wh0.z*hv.z + wh0.w*hv.w;
            acc1[bi] += wi1.x*xv.x + wi1.y*xv.y + wi1.z*xv.z + wi1.w*xv.w
                      + wh1.x*hv.x + wh1.y*hv.y + wh1.z*hv.z + wh1.w*hv.w;
            acc2[bi] += wi2.x*xv.x + wi2.y*xv.y + wi2.z*xv.z + wi2.w*xv.w
                      + wh2.x*hv.x + wh2.y*hv.y + wh2.z*hv.z + wh2.w*hv.w;
            acc3[bi] += wi3.x*xv.x + wi3.y*xv.y + wi3.z*xv.z + wi3.w*xv.w
                      + wh3.x*hv.x + wh3.y*hv.y + wh3.z*hv.z + wh3.w*hv.w;
        }
    }
    #pragma unroll
    for (int bi = 0; bi < 8; bi++) {
        float c_in = memory[(b0 + bi) * 256 + 128 + j];
        float cn = sigm_(acc1[bi]) * c_in + sigm_(acc0[bi]) * tanh_(acc2[bi]);
        float hn = sigm_(acc3[bi]) * tanh_(cn);
        mem_out[(b0 + bi) * 256 + j] = hn;
        mem_out[(b0 + bi) * 256 + 128 + j] = cn;
    }
}

// ---------------- K5: GRU over 20 steps (8 batch / block, 128 threads) --------
__global__ __launch_bounds__(128)
void k_gru(const int* __restrict__ text, const float* __restrict__ bhh) {
    int j = threadIdx.x;
    int b0 = blockIdx.x * 8;
    __shared__ __align__(16) float s_ht[8 * 128];
    __shared__ __align__(16) int s_w[8 * 20];
    for (int idx = j; idx < 160; idx += 128) s_w[idx] = text[b0 * 20 + idx];
    #pragma unroll
    for (int bi = 0; bi < 8; bi++) s_ht[bi * 128 + j] = 0.f;
    float htj[8];
    #pragma unroll
    for (int bi = 0; bi < 8; bi++) htj[bi] = 0.f;
    float bh_r = bhh[j], bh_z = bhh[128 + j], bh_n = bhh[256 + j];
    __syncthreads();

    for (int tt = 0; tt < 20; tt++) {
        float ar[8], az[8], an[8];
        #pragma unroll
        for (int bi = 0; bi < 8; bi++) { ar[bi] = bh_r; az[bi] = bh_z; an[bi] = bh_n; }
        for (int k = 0; k < 128; k += 4) {
            int kc = k >> 2;
            float4 w4r = *(const float4*)(g_gwhhT + kc * 1536 + j * 4);
            float4 w4z = *(const float4*)(g_gwhhT + kc * 1536 + (128 + j) * 4);
            float4 w4n = *(const float4*)(g_gwhhT + kc * 1536 + (256 + j) * 4);
            #pragma unroll
            for (int bi = 0; bi < 8; bi++) {
                float4 hv = *(const float4*)(s_ht + bi * 128 + k);
                ar[bi] += w4r.x*hv.x + w4r.y*hv.y + w4r.z*hv.z + w4r.w*hv.w;
                az[bi] += w4z.x*hv.x + w4z.y*hv.y + w4z.z*hv.z + w4z.w*hv.w;
                an[bi] += w4n.x*hv.x + w4n.y*hv.y + w4n.z*hv.z + w4n.w*hv.w;
            }
        }
        __syncthreads();
        #pragma unroll
        for (int bi = 0; bi < 8; bi++) {
            const float* gi = g_GI + s_w[bi * 20 + tt] * 384;
            float r = sigm_(gi[j] + ar[bi]);
            float z = sigm_(gi[128 + j] + az[bi]);
            float n = tanh_(gi[256 + j] + r * an[bi]);
            float h = (1.f - z) * n + z * htj[bi];
            htj[bi] = h;
            s_ht[bi * 128 + j] = h;
        }
        __syncthreads();
    }
    #pragma unroll
    for (int bi = 0; bi < 8; bi++) g_ht[(b0 + bi) * 128 + j] = htj[bi];
}

// ---------------- K6: actor/critic heads (16 batch / block, 256 threads) -----
__global__ __launch_bounds__(256)
void k_heads(const float* __restrict__ mem,
             const float* __restrict__ ab1, const float* __restrict__ aw2,
             const float* __restrict__ ab2, const float* __restrict__ cb1,
             const float* __restrict__ cw2, const float* __restrict__ cb2,
             float* __restrict__ lp, float* __restrict__ value) {
    int tid = threadIdx.x;
    int b0 = blockIdx.x * 16;
    __shared__ __align__(16) float s_emb[16 * 256];
    __shared__ __align__(16) float s_a1[16 * 256];
    __shared__ __align__(16) float s_logits[16 * 8];

    for (int idx = tid; idx < 16 * 128; idx += 256) {
        int bi = idx >> 7, k = idx & 127;
        s_emb[bi * 256 + k]       = mem[(b0 + bi) * 256 + k];
        s_emb[bi * 256 + 128 + k] = g_ht[(b0 + bi) * 128 + k];
    }
    __syncthreads();

    // actor layer 1
    {
        float acc[16];
        float bb = ab1[tid];
        #pragma unroll
        for (int bi = 0; bi < 16; bi++) acc[bi] = bb;
        for (int k = 0; k < 256; k += 4) {
            float4 w4 = *(const float4*)(g_aw1T + (k >> 2) * 1024 + tid * 4);
            #pragma unroll
            for (int bi = 0; bi < 16; bi++) {
                float4 e = *(const float4*)(s_emb + bi * 256 + k);
                acc[bi] += w4.x*e.x + w4.y*e.y + w4.z*e.z + w4.w*e.w;
            }
        }
        #pragma unroll
        for (int bi = 0; bi < 16; bi++) s_a1[bi * 256 + tid] = tanh_(acc[bi]);
    }
    __syncthreads();

    int warp = tid >> 5, lane = tid & 31;
    for (int bi = warp * 2; bi < warp * 2 + 2; bi++) {
        for (int a = 0; a < 7; a++) {
            float s = 0.f;
            for (int k = lane; k < 256; k += 32) s += aw2[a * 256 + k] * s_a1[bi * 256 + k];
            #pragma unroll
            for (int off = 16; off; off >>= 1) s += __shfl_xor_sync(0xffffffffu, s, off);
            if (lane == 0) s_logits[bi * 8 + a] = s + ab2[a];
        }
    }
    __syncthreads();

    // critic layer 1 (reuses s_a1)
    {
        float acc[16];
        float bb = cb1[tid];
        #pragma unroll
        for (int bi = 0; bi < 16; bi++) acc[bi] = bb;
        for (int k = 0; k < 256; k += 4) {
            float4 w4 = *(const float4*)(g_cw1T + (k >> 2) * 1024 + tid * 4);
            #pragma unroll
            for (int bi = 0; bi < 16; bi++) {
                float4 e = *(const float4*)(s_emb + bi * 256 + k);
                acc[bi] += w4.x*e.x + w4.y*e.y + w4.z*e.z + w4.w*e.w;
            }
        }
        #pragma unroll
        for (int bi = 0; bi < 16; bi++) s_a1[bi * 256 + tid] = tanh_(acc[bi]);
    }
    if (tid < 16) {
        float m = -1e30f;
        #pragma unroll
        for (int a = 0; a < 7; a++) m = fmaxf(m, s_logits[tid * 8 + a]);
        float sum = 0.f;
        #pragma unroll
        for (int a = 0; a < 7; a++) sum += expf(s_logits[tid * 8 + a] - m);
        float lse = m + logf(sum);
        #pragma unroll
        for (int a = 0; a < 7; a++) lp[(b0 + tid) * 7 + a] = s_logits[tid * 8 + a] - lse;
    }
    __syncthreads();

    for (int bi = warp * 2; bi < warp * 2 + 2; bi++) {
        float s = 0.f;
        for (int k = lane; k < 256; k += 32) s += cw2[k] * s_a1[bi * 256 + k];
        #pragma unroll
        for (int off = 16; off; off >>= 1) s += __shfl_xor_sync(0xffffffffu, s, off);
        if (lane == 0) value[b0 + bi] = s + cb2[0];
    }
}

// ---------------- launch ----------------
extern "C" void kernel_launch(void* const* d_in, const int* in_sizes, int n_in,
                              void* d_out, int out_size) {
    const int*   image  = (const int*)  d_in[0];
    const float* memory = (const float*)d_in[1];
    const int*   text   = (const int*)  d_in[2];
    const float* obj_e  = (const float*)d_in[3];
    const float* col_e  = (const float*)d_in[4];
    const float* st_e   = (const float*)d_in[5];
    const float* c1w    = (const float*)d_in[6];
    const float* c1b    = (const float*)d_in[7];
    const float* c2w    = (const float*)d_in[8];
    const float* c2b    = (const float*)d_in[9];
    const float* c3w    = (const float*)d_in[10];
    const float* c3b    = (const float*)d_in[11];
    const float* lwih   = (const float*)d_in[12];
    const float* lwhh   = (const float*)d_in[13];
    const float* lbih   = (const float*)d_in[14];
    const float* lbhh   = (const float*)d_in[15];
    const float* wemb   = (const float*)d_in[16];
    const float* gwih   = (const float*)d_in[17];
    const float* gwhh   = (const float*)d_in[18];
    const float* gbih   = (const float*)d_in[19];
    const float* gbhh   = (const float*)d_in[20];
    const float* aw1    = (const float*)d_in[21];
    const float* ab1    = (const float*)d_in[22];
    const float* aw2    = (const float*)d_in[23];
    const float* ab2    = (const float*)d_in[24];
    const float* cw1    = (const float*)d_in[25];
    const float* cb1    = (const float*)d_in[26];
    const float* cw2    = (const float*)d_in[27];
    const float* cb2    = (const float*)d_in[28];

    const int B = in_sizes[1] / 256;   // 8192
    float* out   = (float*)d_out;
    float* lp    = out;                 // (B,7)
    float* value = out + (size_t)B * 7; // (B,)
    float* memo  = out + (size_t)B * 8; // (B,256)

    float* wihT; cudaGetSymbolAddress((void**)&wihT, g_wihT);
    float* whhT; cudaGetSymbolAddress((void**)&whhT, g_whhT);
    float* gwhhT; cudaGetSymbolAddress((void**)&gwhhT, g_gwhhT);
    float* aw1T; cudaGetSymbolAddress((void**)&aw1T, g_aw1T);
    float* cw1T; cudaGetSymbolAddress((void**)&cw1T, g_cw1T);
    float* w2T; cudaGetSymbolAddress((void**)&w2T, g_w2T);
    float* w3T; cudaGetSymbolAddress((void**)&w3T, g_w3T);

    k_xpose<<<256, 256>>>(lwih, wihT, 512, 128);
    k_xpose<<<256, 256>>>(lwhh, whhT, 512, 128);
    k_xpose<<<192, 256>>>(gwhh, gwhhT, 384, 128);
    k_xpose<<<256, 256>>>(aw1, aw1T, 256, 256);
    k_xpose<<<256, 256>>>(cw1, cw1T, 256, 256);
    k_xpose<<<64, 256>>>(c2w, w2T, 64, 256);
    k_xpose<<<128, 256>>>(c3w, w3T, 128, 256);
    k_build_t1<<<4 * 132, 64>>>(obj_e, col_e, st_e, c1w);
    k_build_gi<<<100, 384>>>(wemb, gwih, gbih);

    k_conv<<<B, 128>>>(image, c1b, c2b, c3b);
    k_lstm<<<B / 8, 128>>>(memory, lbih, lbhh, memo);
    k_gru<<<B / 8, 128>>>(text, gbhh);
    k_heads<<<B / 16, 256>>>(memo, ab1, aw2, ab2, cb1, cw2, cb2, lp, value);
}